// round 16
// baseline (speedup 1.0000x reference)
#include <cuda_runtime.h>
#include <cuda_bf16.h>
#include <cstddef>
#include <cstdint>

#define BB 2
#define SS 2048
#define DD 1024
#define HH 16
#define DK 64
#define BSM (BB*SS)
#define NSPLIT 16

typedef unsigned long long u64;

__device__ float g_Q[(size_t)BB*HH*SS*DK];
__device__ float g_K[(size_t)BB*HH*SS*DK];
__device__ float g_V[(size_t)BB*HH*SS*DK];
__device__ float g_X[(size_t)BB*SS*DD];
__device__ float g_Tp[(size_t)NSPLIT*32*64*64];
__device__ float g_T[(size_t)32*64*64];
__device__ int   g_mflag[2*32*32];
__device__ __nv_bfloat16 g_Whi[(size_t)4*DD*DD];
__device__ __nv_bfloat16 g_Wlo[(size_t)4*DD*DD];

// ----- fp32x2 helpers -----
__device__ __forceinline__ u64 pack2(float lo, float hi) {
    u64 r;
    asm("mov.b64 %0, {%1, %2};" : "=l"(r)
        : "r"(__float_as_uint(lo)), "r"(__float_as_uint(hi)));
    return r;
}
__device__ __forceinline__ u64 bcast2(float x) { return pack2(x, x); }
__device__ __forceinline__ void fma2(u64 &d, u64 a, u64 b) {
    asm("fma.rn.f32x2 %0, %1, %2, %0;" : "+l"(d) : "l"(a), "l"(b));
}
__device__ __forceinline__ float2 unpack2(u64 v) {
    unsigned lo, hi;
    asm("mov.b64 {%0, %1}, %2;" : "=r"(lo), "=r"(hi) : "l"(v));
    return make_float2(__uint_as_float(lo), __uint_as_float(hi));
}

// ----- MMA helpers -----
__device__ __forceinline__ uint32_t smem_u32(const void* p) {
    uint32_t a;
    asm("{ .reg .u64 t; cvta.to.shared.u64 t, %1; cvt.u32.u64 %0, t; }"
        : "=r"(a) : "l"(p));
    return a;
}
__device__ __forceinline__ void ldsm_x4(uint32_t* r, uint32_t addr) {
    asm volatile("ldmatrix.sync.aligned.m8n8.x4.shared.b16 {%0,%1,%2,%3}, [%4];"
        : "=r"(r[0]), "=r"(r[1]), "=r"(r[2]), "=r"(r[3]) : "r"(addr));
}
__device__ __forceinline__ void mma_bf16(float* d, const uint32_t* a, const uint32_t* b) {
    asm volatile("mma.sync.aligned.m16n8k16.row.col.f32.bf16.bf16.f32 "
        "{%0,%1,%2,%3}, {%4,%5,%6,%7}, {%8,%9}, {%0,%1,%2,%3};"
        : "+f"(d[0]), "+f"(d[1]), "+f"(d[2]), "+f"(d[3])
        : "r"(a[0]), "r"(a[1]), "r"(a[2]), "r"(a[3]), "r"(b[0]), "r"(b[1]));
}
__device__ __forceinline__ void cp16(uint32_t dst, const void* src) {
    asm volatile("cp.async.cg.shared.global [%0], [%1], 16;" :: "r"(dst), "l"(src));
}
#define CP_COMMIT() asm volatile("cp.async.commit_group;")
#define CP_WAIT(n)  asm volatile("cp.async.wait_group %0;" :: "n"(n))

// 128(M) x 256(N) CTA tile, BK=32, bf16 rows padded to 80B.
#define TSTRIDE_B 80
#define TILE_A_B  (128*TSTRIDE_B)                 // 10240
#define TILE_W_B  (256*TSTRIDE_B)                 // 20480
#define BUF_B     (2*TILE_A_B + 2*TILE_W_B)       // 61440
#define SMEM_GEMM (2*BUF_B)                       // 122880

__device__ __forceinline__ void split4(float4 v, uint2& hi, uint2& lo)
{
    __nv_bfloat16 h0 = __float2bfloat16(v.x), h1 = __float2bfloat16(v.y);
    __nv_bfloat16 h2 = __float2bfloat16(v.z), h3 = __float2bfloat16(v.w);
    __nv_bfloat16 l0 = __float2bfloat16(v.x - __bfloat162float(h0));
    __nv_bfloat16 l1 = __float2bfloat16(v.y - __bfloat162float(h1));
    __nv_bfloat16 l2 = __float2bfloat16(v.z - __bfloat162float(h2));
    __nv_bfloat16 l3 = __float2bfloat16(v.w - __bfloat162float(h3));
    __nv_bfloat162 H0 = __halves2bfloat162(h0, h1), H1 = __halves2bfloat162(h2, h3);
    __nv_bfloat162 L0 = __halves2bfloat162(l0, l1), L1 = __halves2bfloat162(l2, l3);
    hi.x = *(unsigned*)&H0; hi.y = *(unsigned*)&H1;
    lo.x = *(unsigned*)&L0; lo.y = *(unsigned*)&L1;
}

__global__ __launch_bounds__(256)
void split_weights_kernel(const float* __restrict__ Wq, const float* __restrict__ Wk,
                          const float* __restrict__ Wv, const float* __restrict__ Wo)
{
    const int which = blockIdx.y;
    const float* src = (which == 0) ? Wq : (which == 1) ? Wk : (which == 2) ? Wv : Wo;
    __nv_bfloat16* hi = g_Whi + (size_t)which * DD * DD;
    __nv_bfloat16* lo = g_Wlo + (size_t)which * DD * DD;
    int i = blockIdx.x * blockDim.x + threadIdx.x;
    uint2 h, l;
    split4(((const float4*)src)[i], h, l);
    ((uint2*)hi)[i] = h;
    ((uint2*)lo)[i] = l;
}

// ---------------------------------------------------------------------------
// GEMM core: 256 threads (8 warps, 2m x 4n of 64x64), CTA tile 128x256,
// BK=32, fp32 A split in-kernel, pre-split bf16 W, 3-pass split MMA,
// STSA interleaved between ks halves. 2 warps per SMSP hide ldsm latency.
// ---------------------------------------------------------------------------
template<bool HEADSPLIT>
__device__ __forceinline__
void gemm_body(const float* __restrict__ gA, const char* gWh, const char* gWl,
               const float* __restrict__ Bias, float* __restrict__ Dst,
               int bm, int bn, char* smem)
{
    const int tid  = threadIdx.x;
    const int wid  = tid >> 5;
    const int lane = tid & 31;
    const uint32_t sA = smem_u32(smem);

    const int arow0 = tid >> 3;          // 0..31, rows +i*32 (4 iters)
    const int ac4   = (tid & 7) * 4;     // fp32 col
    const int wrow0 = tid >> 2;          // 0..63, rows +i*64 (4 iters)
    const int wcc   = (tid & 3) * 16;    // byte col

    float4 rA[4];

    #define LOADA(ck) do {                                                    \
        _Pragma("unroll")                                                     \
        for (int i = 0; i < 4; ++i)                                           \
            rA[i] = *(const float4*)(gA + (size_t)(arow0 + i*32) * DD         \
                                        + (ck)*32 + ac4);                     \
    } while (0)
    #define STSA(buf) do {                                                    \
        _Pragma("unroll")                                                     \
        for (int i = 0; i < 4; ++i) {                                         \
            uint2 h, l; split4(rA[i], h, l);                                  \
            char* base = smem + (buf)*BUF_B + (arow0 + i*32)*TSTRIDE_B + ac4*2;\
            *(uint2*)(base) = h; *(uint2*)(base + TILE_A_B) = l;              \
        }                                                                     \
    } while (0)
    #define STAGEW(buf, ck) do {                                              \
        _Pragma("unroll")                                                     \
        for (int i = 0; i < 4; ++i) {                                         \
            const int row = wrow0 + i*64;                                     \
            const size_t go = (size_t)row * 2048 + (ck)*64 + wcc;             \
            uint32_t d = sA + (buf)*BUF_B + 2*TILE_A_B + row*TSTRIDE_B + wcc; \
            cp16(d, gWh + go);                                                \
            cp16(d + TILE_W_B, gWl + go);                                     \
        }                                                                     \
    } while (0)

    const int wm = (wid >> 2) * 64;      // 2 m-groups
    const int wn = (wid & 3) * 64;       // 4 n-groups
    const int laA_row = lane & 15;
    const int laA_k   = (lane >> 4) << 3;
    const int laB_row = ((lane >> 4) << 3) + (lane & 7);
    const int laB_k   = ((lane >> 3) & 1) << 3;

    float acc[4][8][4] = {};

    LOADA(0);
    STAGEW(0, 0);
    CP_COMMIT();
    STSA(0);

    for (int ck = 0; ck < 32; ++ck) {
        const int buf = ck & 1;
        if (ck + 1 < 32) {
            LOADA(ck + 1);
            STAGEW(buf ^ 1, ck + 1);
            CP_COMMIT();
            CP_WAIT(1);
        } else {
            CP_WAIT(0);
        }
        __syncthreads();

        const uint32_t tAh = sA + buf*BUF_B;
        const uint32_t tAl = tAh + TILE_A_B;
        const uint32_t tWh = tAh + 2*TILE_A_B;
        const uint32_t tWl = tWh + TILE_W_B;

        #pragma unroll
        for (int ks = 0; ks < 32; ks += 16) {
            uint32_t a_h[4][4], a_l[4][4];
            #pragma unroll
            for (int mi = 0; mi < 4; ++mi) {
                const uint32_t ao = (uint32_t)((wm + mi*16 + laA_row) * TSTRIDE_B
                                               + (ks + laA_k) * 2);
                ldsm_x4(a_h[mi], tAh + ao);
                ldsm_x4(a_l[mi], tAl + ao);
            }
            #pragma unroll
            for (int j = 0; j < 4; ++j) {
                uint32_t b_h[4], b_l[4];
                const uint32_t bo = (uint32_t)((wn + j*16 + laB_row) * TSTRIDE_B
                                               + (ks + laB_k) * 2);
                ldsm_x4(b_h, tWh + bo);
                ldsm_x4(b_l, tWl + bo);
                #pragma unroll
                for (int mi = 0; mi < 4; ++mi) {
                    #pragma unroll
                    for (int sub = 0; sub < 2; ++sub) {
                        float* d = acc[mi][j*2 + sub];
                        mma_bf16(d, a_h[mi], &b_h[sub*2]);
                        mma_bf16(d, a_h[mi], &b_l[sub*2]);
                        mma_bf16(d, a_l[mi], &b_h[sub*2]);
                    }
                }
            }
            if (ks == 0 && ck + 1 < 32) STSA(buf ^ 1);
        }
        __syncthreads();
    }

    // Epilogue. Warp owns rows [wm + mi*16 .. +16), cols [wn + nj*8 ..).
    // NOTE: warp-tile rows are 64 within the 128-row CTA tile (mi<4 -> 64 rows).
    #pragma unroll
    for (int mi = 0; mi < 4; ++mi) {
        #pragma unroll
        for (int nj = 0; nj < 8; ++nj) {
            const int col = bn + wn + nj*8 + (lane & 3)*2;
            const int r0  = bm + wm + mi*16 + (lane >> 2);
            const float b0 = Bias[col], b1 = Bias[col + 1];
            const float* d = acc[mi][nj];
            float2 o0 = { d[0] + b0, d[1] + b1 };
            float2 o1 = { d[2] + b0, d[3] + b1 };
            if (HEADSPLIT) {
                const int h = col >> 6, dk = col & 63;
                const int bA = r0 >> 11, s0 = r0 & (SS - 1);
                *(float2*)(Dst + (((size_t)(bA*HH + h) * SS + s0) * DK + dk)) = o0;
                const int r1 = r0 + 8;
                const int bB = r1 >> 11, s1 = r1 & (SS - 1);
                *(float2*)(Dst + (((size_t)(bB*HH + h) * SS + s1) * DK + dk)) = o1;
            } else {
                *(float2*)(Dst + (size_t)r0 * DD + col)     = o0;
                *(float2*)(Dst + (size_t)(r0+8) * DD + col) = o1;
            }
        }
    }
    #undef LOADA
    #undef STSA
    #undef STAGEW
}

// Projection GEMM: zbase+blockIdx.z selects 0=Q,1=K,2=V.
__global__ __launch_bounds__(256)
void gemm_proj_kernel(int zbase,
                      const float* __restrict__ q_in, const float* __restrict__ k_in,
                      const float* __restrict__ v_in, const float* __restrict__ bq,
                      const float* __restrict__ bk, const float* __restrict__ bv)
{
    extern __shared__ char smem[];
    const int z  = zbase + blockIdx.z;
    const int bm = blockIdx.y * 128;
    const int bn = blockIdx.x * 256;
    const float* A   = (z == 0) ? q_in : (z == 1) ? k_in : v_in;
    const float* Bia = (z == 0) ? bq : (z == 1) ? bk : bv;
    float* Dst       = (z == 0) ? g_Q : (z == 1) ? g_K : g_V;
    gemm_body<true>(A + (size_t)bm * DD,
                    (const char*)(g_Whi + (size_t)z*DD*DD) + (size_t)bn * 2048,
                    (const char*)(g_Wlo + (size_t)z*DD*DD) + (size_t)bn * 2048,
                    Bia, Dst, bm, bn, smem);
}

__global__ __launch_bounds__(256)
void gemm_out_kernel(const float* __restrict__ bo, float* __restrict__ out)
{
    extern __shared__ char smem[];
    const int bm = blockIdx.y * 128;
    const int bn = blockIdx.x * 256;
    gemm_body<false>(g_X + (size_t)bm * DD,
                     (const char*)(g_Whi + (size_t)3*DD*DD) + (size_t)bn * 2048,
                     (const char*)(g_Wlo + (size_t)3*DD*DD) + (size_t)bn * 2048,
                     bo, out, bm, bn, smem);
}

// ----- Stage A: K^T V partials, double-buffered cp.async -----
__global__ __launch_bounds__(256)
void kv_outer_kernel()
{
    const int bh = blockIdx.x;
    const int sp = blockIdx.y;
    const float* Kh = g_K + (size_t)bh * SS * DK;
    const float* Vh = g_V + (size_t)bh * SS * DK;

    __shared__ float Ks[2][32][68];
    __shared__ float Vs[2][32][68];

    const int tid = threadIdx.x;
    const int tx = tid & 15;
    const int ty = tid >> 4;
    const int lr  = tid >> 4;
    const int lc4 = (tid & 15) * 4;

    const int s0 = sp * (SS / NSPLIT);
    const int NCH = SS / NSPLIT / 32;

    #define KVSTAGE(buf, c) do {                                              \
        _Pragma("unroll")                                                     \
        for (int it = 0; it < 2; ++it) {                                      \
            const int r = lr + it * 16;                                       \
            const size_t go = (size_t)(s0 + (c)*32 + r) * DK + lc4;           \
            cp16(smem_u32(&Ks[buf][r][lc4]), &Kh[go]);                        \
            cp16(smem_u32(&Vs[buf][r][lc4]), &Vh[go]);                        \
        }                                                                     \
    } while (0)

    u64 acc[4][2] = {};

    KVSTAGE(0, 0);
    CP_COMMIT();

    for (int c = 0; c < NCH; ++c) {
        const int buf = c & 1;
        if (c + 1 < NCH) {
            KVSTAGE(buf ^ 1, c + 1);
            CP_COMMIT();
            CP_WAIT(1);
        } else {
            CP_WAIT(0);
        }
        __syncthreads();
        #pragma unroll
        for (int s = 0; s < 32; ++s) {
            float4 a = *(const float4*)&Ks[buf][s][ty*4];
            const u64* vp = (const u64*)&Vs[buf][s][tx*4];
            u64 v0 = vp[0], v1 = vp[1];
            fma2(acc[0][0], bcast2(a.x), v0); fma2(acc[0][1], bcast2(a.x), v1);
            fma2(acc[1][0], bcast2(a.y), v0); fma2(acc[1][1], bcast2(a.y), v1);
            fma2(acc[2][0], bcast2(a.z), v0); fma2(acc[2][1], bcast2(a.z), v1);
            fma2(acc[3][0], bcast2(a.w), v0); fma2(acc[3][1], bcast2(a.w), v1);
        }
        __syncthreads();
    }
    #undef KVSTAGE

    float* dst = g_Tp + (size_t)(sp * 32 + bh) * 4096;
    #pragma unroll
    for (int i = 0; i < 4; ++i) {
        float2 p0 = unpack2(acc[i][0]);
        float2 p1 = unpack2(acc[i][1]);
        float4 o = { p0.x, p0.y, p1.x, p1.y };
        *(float4*)&dst[(ty*4 + i) * 64 + tx*4] = o;
    }
}

__global__ __launch_bounds__(128)
void reduce_T_kernel()
{
    const int bh = blockIdx.x;
    const int i  = blockIdx.y * 128 + threadIdx.x;
    float4 s = {0.f, 0.f, 0.f, 0.f};
    #pragma unroll
    for (int sp = 0; sp < NSPLIT; ++sp) {
        const float4 p = *(const float4*)&g_Tp[(size_t)(sp*32 + bh)*4096 + i*4];
        s.x += p.x; s.y += p.y; s.z += p.z; s.w += p.w;
    }
    float4 o = { s.x*0.125f, s.y*0.125f, s.z*0.125f, s.w*0.125f };
    *(float4*)&g_T[(size_t)bh*4096 + i*4] = o;
}

__global__ __launch_bounds__(256)
void mask_scan_kernel(const int* __restrict__ mask)
{
    const int kt = blockIdx.x, qt = blockIdx.y, b = blockIdx.z;
    const int* mp = mask + (size_t)b * SS * SS + (size_t)qt * 64 * SS + kt * 64;
    __shared__ int s_bad;
    if (threadIdx.x == 0) s_bad = 0;
    __syncthreads();
    const int r  = threadIdx.x >> 2;
    const int c0 = (threadIdx.x & 3) * 16;
    bool bad = false;
    #pragma unroll
    for (int j = 0; j < 4; ++j) {
        int4 v = *(const int4*)&mp[(size_t)r * SS + c0 + j*4];
        if (v.x == 0 || v.y == 0 || v.z == 0 || v.w == 0) bad = true;
    }
    if (bad) s_bad = 1;
    __syncthreads();
    if (threadIdx.x == 0) g_mflag[(b*32 + qt)*32 + kt] = s_bad;
}

// ----- Stage B: qkv = Q @ T (+ corrections), softmax over DK, write fp32 X -----
__global__ __launch_bounds__(256)
void qt_softmax_kernel(const int* __restrict__ mask)
{
    const int qt = blockIdx.x;
    const int bh = blockIdx.y;
    const int b  = bh >> 4;
    const int h  = bh & (HH - 1);
    const int q0 = qt * 64;

    const float* Qh = g_Q + (size_t)bh * SS * DK;

    __shared__ float Qs[64][68];
    __shared__ float Ts[64][68];
    __shared__ float CK[16][68];
    __shared__ float CV[16][68];
    __shared__ int s_flags[32];
    __shared__ int s_any;

    const int tid = threadIdx.x;

    #pragma unroll
    for (int it = 0; it < 4; ++it) {
        const int lin = tid + it * 256;
        const int d4 = lin >> 6;
        const int q  = lin & 63;
        float4 v = *(const float4*)&Qh[(size_t)(q0 + q) * DK + d4*4];
        Qs[d4*4+0][q] = v.x; Qs[d4*4+1][q] = v.y;
        Qs[d4*4+2][q] = v.z; Qs[d4*4+3][q] = v.w;
    }
    {
        const float* Tb = g_T + (size_t)bh * 4096;
        #pragma unroll
        for (int it = 0; it < 4; ++it) {
            const int lin = tid + it * 256;
            const int d1 = lin >> 4;
            const int c4 = (lin & 15) * 4;
            *(float4*)&Ts[d1][c4] = *(const float4*)(Tb + d1 * 64 + c4);
        }
    }

    if (tid == 0) s_any = 0;
    __syncthreads();
    if (tid < 32) {
        int f = g_mflag[(b*32 + qt)*32 + tid];
        s_flags[tid] = f;
        if (f) s_any = 1;
    }
    __syncthreads();

    const int tx = tid & 15;
    const int ty = tid >> 4;

    u64 acc[4][2] = {};
    #pragma unroll
    for (int d1 = 0; d1 < 64; ++d1) {
        float4 a = *(const float4*)&Qs[d1][ty*4];
        const u64* tp = (const u64*)&Ts[d1][tx*4];
        u64 t0 = tp[0], t1 = tp[1];
        fma2(acc[0][0], bcast2(a.x), t0); fma2(acc[0][1], bcast2(a.x), t1);
        fma2(acc[1][0], bcast2(a.y), t0); fma2(acc[1][1], bcast2(a.y), t1);
        fma2(acc[2][0], bcast2(a.z), t0); fma2(acc[2][1], bcast2(a.z), t1);
        fma2(acc[3][0], bcast2(a.w), t0); fma2(acc[3][1], bcast2(a.w), t1);
    }

    if (s_any) {
        const float* Kh = g_K + (size_t)bh * SS * DK;
        const float* Vh = g_V + (size_t)bh * SS * DK;
        const int* mb = mask + (size_t)b * SS * SS;
        for (int kt = 0; kt < 32; ++kt) {
            if (!s_flags[kt]) continue;
            for (int sub = 0; sub < 4; ++sub) {
                const int kbase = kt*64 + sub*16;
                __syncthreads();
                {
                    const int r  = tid >> 4;
                    const int c4 = (tid & 15) * 4;
                    *(float4*)&CK[r][c4] = *(const float4*)&Kh[(size_t)(kbase + r) * DK + c4];
                    *(float4*)&CV[r][c4] = *(const float4*)&Vh[(size_t)(kbase + r) * DK + c4];
                }
                __syncthreads();
                for (int kk = 0; kk < 16; ++kk) {
                    const u64* vp = (const u64*)&CV[kk][tx*4];
                    u64 v0 = vp[0], v1 = vp[1];
                    #pragma unroll
                    for (int qi = 0; qi < 4; ++qi) {
                        const int q = q0 + ty*4 + qi;
                        if (mb[(size_t)q * SS + kbase + kk] == 0) {
                            float s = 0.f;
                            for (int d1 = 0; d1 < 64; ++d1)
                                s += Qs[d1][ty*4 + qi] * CK[kk][d1];
                            const float coef = -1e9f - s * 0.125f;
                            u64 cz = bcast2(coef);
                            fma2(acc[qi][0], cz, v0);
                            fma2(acc[qi][1], cz, v1);
                        }
                    }
                }
            }
        }
    }

    #pragma unroll
    for (int i = 0; i < 4; ++i) {
        float2 pa = unpack2(acc[i][0]);
        float2 pb = unpack2(acc[i][1]);
        float v0 = pa.x, v1 = pa.y, v2 = pb.x, v3 = pb.y;
        float m = fmaxf(fmaxf(v0, v1), fmaxf(v2, v3));
        #pragma unroll
        for (int off = 8; off >= 1; off >>= 1)
            m = fmaxf(m, __shfl_xor_sync(0xffffffffu, m, off, 16));
        float e0 = __expf(v0 - m);
        float e1 = __expf(v1 - m);
        float e2 = __expf(v2 - m);
        float e3 = __expf(v3 - m);
        float sum = e0 + e1 + e2 + e3;
        #pragma unroll
        for (int off = 8; off >= 1; off >>= 1)
            sum += __shfl_xor_sync(0xffffffffu, sum, off, 16);
        const float inv = 1.0f / sum;
        float4 o = { e0*inv, e1*inv, e2*inv, e3*inv };
        const int s = q0 + ty*4 + i;
        *(float4*)&g_X[((size_t)b * SS + s) * DD + h * DK + tx*4] = o;
    }
}

// ----- Launch -----
extern "C" void kernel_launch(void* const* d_in, const int* in_sizes, int n_in,
                              void* d_out, int out_size)
{
    (void)in_sizes; (void)n_in; (void)out_size;
    const float* k_in = (const float*)d_in[0];
    const float* q_in = (const float*)d_in[1];
    const float* v_in = (const float*)d_in[2];
    const int*   mask = (const int*)  d_in[3];
    const float* Wq = (const float*)d_in[4];
    const float* bq = (const float*)d_in[5];
    const float* Wk = (const float*)d_in[6];
    const float* bk = (const float*)d_in[7];
    const float* Wv = (const float*)d_in[8];
    const float* bv = (const float*)d_in[9];
    const float* Wo = (const float*)d_in[10];
    const float* bo = (const float*)d_in[11];
    float* out = (float*)d_out;

    static bool s_init = false;
    static cudaStream_t s2, s3;
    static cudaEvent_t evF, evJ, evKV, evT;
    if (!s_init) {
        cudaStreamCreate(&s2);
        cudaStreamCreate(&s3);
        cudaEventCreateWithFlags(&evF, cudaEventDisableTiming);
        cudaEventCreateWithFlags(&evJ, cudaEventDisableTiming);
        cudaEventCreateWithFlags(&evKV, cudaEventDisableTiming);
        cudaEventCreateWithFlags(&evT, cudaEventDisableTiming);
        cudaFuncSetAttribute((const void*)gemm_proj_kernel,
                             cudaFuncAttributeMaxDynamicSharedMemorySize, SMEM_GEMM);
        cudaFuncSetAttribute((const void*)gemm_out_kernel,
                             cudaFuncAttributeMaxDynamicSharedMemorySize, SMEM_GEMM);
        cudaFuncSetAttribute((const void*)gemm_proj_kernel,
                             cudaFuncAttributePreferredSharedMemoryCarveout, 100);
        cudaFuncSetAttribute((const void*)gemm_out_kernel,
                             cudaFuncAttributePreferredSharedMemoryCarveout, 100);
        s_init = true;
    }

    const int nW4 = DD * DD / 4;

    // Fork 1: mask_scan depends only on mask -> side stream s2.
    cudaEventRecord(evF, 0);
    cudaStreamWaitEvent(s2, evF, 0);
    mask_scan_kernel<<<dim3(32, 32, 2), 256, 0, s2>>>(mask);
    cudaEventRecord(evJ, s2);

    split_weights_kernel<<<dim3(nW4/256, 4), 256>>>(Wq, Wk, Wv, Wo);

    // K,V projections first; kv_outer only needs these.
    gemm_proj_kernel<<<dim3(DD/256, BSM/128, 2), 256, SMEM_GEMM>>>(
        1, q_in, k_in, v_in, bq, bk, bv);
    cudaEventRecord(evKV, 0);

    // Q projection on main stream, overlapped with kv_outer/reduce_T on s3.
    gemm_proj_kernel<<<dim3(DD/256, BSM/128, 1), 256, SMEM_GEMM>>>(
        0, q_in, k_in, v_in, bq, bk, bv);

    cudaStreamWaitEvent(s3, evKV, 0);
    kv_outer_kernel<<<dim3(32, NSPLIT), 256, 0, s3>>>();
    reduce_T_kernel<<<dim3(32, 8), 128, 0, s3>>>();
    cudaEventRecord(evT, s3);

    // Join: qt_softmax needs Q (stream 0 order), T (evT), mask flags (evJ).
    cudaStreamWaitEvent(0, evT, 0);
    cudaStreamWaitEvent(0, evJ, 0);
    qt_softmax_kernel<<<dim3(32, 32), 256>>>(mask);

    gemm_out_kernel<<<dim3(DD/256, BSM/128), 256, SMEM_GEMM>>>(bo, out);
}

// round 17
// speedup vs baseline: 1.1492x; 1.1492x over previous
#include <cuda_runtime.h>
#include <cuda_bf16.h>
#include <cstddef>
#include <cstdint>

#define BB 2
#define SS 2048
#define DD 1024
#define HH 16
#define DK 64
#define BSM (BB*SS)
#define NSPLIT 16

typedef unsigned long long u64;

__device__ float g_Q[(size_t)BB*HH*SS*DK];
__device__ float g_K[(size_t)BB*HH*SS*DK];
__device__ float g_V[(size_t)BB*HH*SS*DK];
__device__ float g_X[(size_t)BB*SS*DD];
__device__ float g_Tp[(size_t)NSPLIT*32*64*64];
__device__ float g_T[(size_t)32*64*64];
__device__ int   g_mflag[2*32*32];
__device__ __nv_bfloat16 g_Whi[(size_t)4*DD*DD];
__device__ __nv_bfloat16 g_Wlo[(size_t)4*DD*DD];

// ----- fp32x2 helpers -----
__device__ __forceinline__ u64 pack2(float lo, float hi) {
    u64 r;
    asm("mov.b64 %0, {%1, %2};" : "=l"(r)
        : "r"(__float_as_uint(lo)), "r"(__float_as_uint(hi)));
    return r;
}
__device__ __forceinline__ u64 bcast2(float x) { return pack2(x, x); }
__device__ __forceinline__ void fma2(u64 &d, u64 a, u64 b) {
    asm("fma.rn.f32x2 %0, %1, %2, %0;" : "+l"(d) : "l"(a), "l"(b));
}
__device__ __forceinline__ float2 unpack2(u64 v) {
    unsigned lo, hi;
    asm("mov.b64 {%0, %1}, %2;" : "=r"(lo), "=r"(hi) : "l"(v));
    return make_float2(__uint_as_float(lo), __uint_as_float(hi));
}

// ----- MMA helpers -----
__device__ __forceinline__ uint32_t smem_u32(const void* p) {
    uint32_t a;
    asm("{ .reg .u64 t; cvta.to.shared.u64 t, %1; cvt.u32.u64 %0, t; }"
        : "=r"(a) : "l"(p));
    return a;
}
__device__ __forceinline__ void ldsm_x4(uint32_t* r, uint32_t addr) {
    asm volatile("ldmatrix.sync.aligned.m8n8.x4.shared.b16 {%0,%1,%2,%3}, [%4];"
        : "=r"(r[0]), "=r"(r[1]), "=r"(r[2]), "=r"(r[3]) : "r"(addr));
}
__device__ __forceinline__ void mma_bf16(float* d, const uint32_t* a, const uint32_t* b) {
    asm volatile("mma.sync.aligned.m16n8k16.row.col.f32.bf16.bf16.f32 "
        "{%0,%1,%2,%3}, {%4,%5,%6,%7}, {%8,%9}, {%0,%1,%2,%3};"
        : "+f"(d[0]), "+f"(d[1]), "+f"(d[2]), "+f"(d[3])
        : "r"(a[0]), "r"(a[1]), "r"(a[2]), "r"(a[3]), "r"(b[0]), "r"(b[1]));
}
__device__ __forceinline__ void cp16(uint32_t dst, const void* src) {
    asm volatile("cp.async.cg.shared.global [%0], [%1], 16;" :: "r"(dst), "l"(src));
}
#define CP_COMMIT() asm volatile("cp.async.commit_group;")
#define CP_WAIT(n)  asm volatile("cp.async.wait_group %0;" :: "n"(n))

#define TSTRIDE_B 80
#define TILE_B    (128*TSTRIDE_B)
#define BUF_B     (4*TILE_B)
#define SMEM_GEMM (2*BUF_B)

__device__ __forceinline__ void split4(float4 v, uint2& hi, uint2& lo)
{
    __nv_bfloat16 h0 = __float2bfloat16(v.x), h1 = __float2bfloat16(v.y);
    __nv_bfloat16 h2 = __float2bfloat16(v.z), h3 = __float2bfloat16(v.w);
    __nv_bfloat16 l0 = __float2bfloat16(v.x - __bfloat162float(h0));
    __nv_bfloat16 l1 = __float2bfloat16(v.y - __bfloat162float(h1));
    __nv_bfloat16 l2 = __float2bfloat16(v.z - __bfloat162float(h2));
    __nv_bfloat16 l3 = __float2bfloat16(v.w - __bfloat162float(h3));
    __nv_bfloat162 H0 = __halves2bfloat162(h0, h1), H1 = __halves2bfloat162(h2, h3);
    __nv_bfloat162 L0 = __halves2bfloat162(l0, l1), L1 = __halves2bfloat162(l2, l3);
    hi.x = *(unsigned*)&H0; hi.y = *(unsigned*)&H1;
    lo.x = *(unsigned*)&L0; lo.y = *(unsigned*)&L1;
}

// which: weight index to split (0..3)
__global__ __launch_bounds__(256)
void split_one_weight_kernel(int which,
                             const float* __restrict__ Wq, const float* __restrict__ Wk,
                             const float* __restrict__ Wv, const float* __restrict__ Wo)
{
    const int w = which + blockIdx.y;
    const float* src = (w == 0) ? Wq : (w == 1) ? Wk : (w == 2) ? Wv : Wo;
    __nv_bfloat16* hi = g_Whi + (size_t)w * DD * DD;
    __nv_bfloat16* lo = g_Wlo + (size_t)w * DD * DD;
    int i = blockIdx.x * blockDim.x + threadIdx.x;
    uint2 h, l;
    split4(((const float4*)src)[i], h, l);
    ((uint2*)hi)[i] = h;
    ((uint2*)lo)[i] = l;
}

// ---------------------------------------------------------------------------
// GEMM core (R12/R15 winner): fp32 A split in-kernel, pre-split bf16 W,
// 128 threads (2x2 warps of 64x64), BK=32, 3-pass split MMA, STSA interleaved.
// ---------------------------------------------------------------------------
template<bool HEADSPLIT>
__device__ __forceinline__
void gemm_body(const float* __restrict__ gA, const char* gWh, const char* gWl,
               const float* __restrict__ Bias, float* __restrict__ Dst,
               int bm, int bn, char* smem)
{
    const int tid  = threadIdx.x;
    const int wid  = tid >> 5;
    const int lane = tid & 31;
    const uint32_t sA = smem_u32(smem);

    const int arow0 = tid >> 3;
    const int ac4   = (tid & 7) * 4;
    const int wrow0 = tid >> 2;
    const int wcc   = (tid & 3) * 16;

    float4 rA[8];

    #define LOADA(ck) do {                                                    \
        _Pragma("unroll")                                                     \
        for (int i = 0; i < 8; ++i)                                           \
            rA[i] = *(const float4*)(gA + (size_t)(arow0 + i*16) * DD         \
                                        + (ck)*32 + ac4);                     \
    } while (0)
    #define STSA(buf) do {                                                    \
        _Pragma("unroll")                                                     \
        for (int i = 0; i < 8; ++i) {                                         \
            uint2 h, l; split4(rA[i], h, l);                                  \
            char* base = smem + (buf)*BUF_B + (arow0 + i*16)*TSTRIDE_B + ac4*2;\
            *(uint2*)(base) = h; *(uint2*)(base + TILE_B) = l;                \
        }                                                                     \
    } while (0)
    #define STAGEW(buf, ck) do {                                              \
        _Pragma("unroll")                                                     \
        for (int i = 0; i < 4; ++i) {                                         \
            const int row = wrow0 + i*32;                                     \
            const size_t go = (size_t)row * 2048 + (ck)*64 + wcc;             \
            uint32_t d = sA + (buf)*BUF_B + row*TSTRIDE_B + wcc;              \
            cp16(d + 2*TILE_B, gWh + go);                                     \
            cp16(d + 3*TILE_B, gWl + go);                                     \
        }                                                                     \
    } while (0)

    const int wm = (wid >> 1) * 64;
    const int wn = (wid & 1) * 64;
    const int laA_row = lane & 15;
    const int laA_k   = (lane >> 4) << 3;
    const int laB_row = ((lane >> 4) << 3) + (lane & 7);
    const int laB_k   = ((lane >> 3) & 1) << 3;

    float acc[4][8][4] = {};

    LOADA(0);
    STAGEW(0, 0);
    CP_COMMIT();
    STSA(0);

    for (int ck = 0; ck < 32; ++ck) {
        const int buf = ck & 1;
        if (ck + 1 < 32) {
            LOADA(ck + 1);
            STAGEW(buf ^ 1, ck + 1);
            CP_COMMIT();
            CP_WAIT(1);
        } else {
            CP_WAIT(0);
        }
        __syncthreads();

        const uint32_t tAh = sA + buf*BUF_B;
        const uint32_t tAl = tAh + TILE_B;
        const uint32_t tWh = tAh + 2*TILE_B;
        const uint32_t tWl = tAh + 3*TILE_B;

        #pragma unroll
        for (int ks = 0; ks < 32; ks += 16) {
            uint32_t a_h[4][4], a_l[4][4];
            #pragma unroll
            for (int mi = 0; mi < 4; ++mi) {
                const uint32_t ao = (uint32_t)((wm + mi*16 + laA_row) * TSTRIDE_B
                                               + (ks + laA_k) * 2);
                ldsm_x4(a_h[mi], tAh + ao);
                ldsm_x4(a_l[mi], tAl + ao);
            }
            #pragma unroll
            for (int j = 0; j < 4; ++j) {
                uint32_t b_h[4], b_l[4];
                const uint32_t bo = (uint32_t)((wn + j*16 + laB_row) * TSTRIDE_B
                                               + (ks + laB_k) * 2);
                ldsm_x4(b_h, tWh + bo);
                ldsm_x4(b_l, tWl + bo);
                #pragma unroll
                for (int mi = 0; mi < 4; ++mi) {
                    #pragma unroll
                    for (int sub = 0; sub < 2; ++sub) {
                        float* d = acc[mi][j*2 + sub];
                        mma_bf16(d, a_h[mi], &b_h[sub*2]);
                        mma_bf16(d, a_h[mi], &b_l[sub*2]);
                        mma_bf16(d, a_l[mi], &b_h[sub*2]);
                    }
                }
            }
            if (ks == 0 && ck + 1 < 32) STSA(buf ^ 1);
        }
        __syncthreads();
    }

    #pragma unroll
    for (int mi = 0; mi < 4; ++mi) {
        #pragma unroll
        for (int nj = 0; nj < 8; ++nj) {
            const int col = bn + wn + nj*8 + (lane & 3)*2;
            const int r0  = bm + wm + mi*16 + (lane >> 2);
            const float b0 = Bias[col], b1 = Bias[col + 1];
            const float* d = acc[mi][nj];
            float2 o0 = { d[0] + b0, d[1] + b1 };
            float2 o1 = { d[2] + b0, d[3] + b1 };
            if (HEADSPLIT) {
                const int h = col >> 6, dk = col & 63;
                const int bA = r0 >> 11, s0 = r0 & (SS - 1);
                *(float2*)(Dst + (((size_t)(bA*HH + h) * SS + s0) * DK + dk)) = o0;
                const int r1 = r0 + 8;
                const int bB = r1 >> 11, s1 = r1 & (SS - 1);
                *(float2*)(Dst + (((size_t)(bB*HH + h) * SS + s1) * DK + dk)) = o1;
            } else {
                *(float2*)(Dst + (size_t)r0 * DD + col)     = o0;
                *(float2*)(Dst + (size_t)(r0+8) * DD + col) = o1;
            }
        }
    }
    #undef LOADA
    #undef STSA
    #undef STAGEW
}

// Projection GEMM: zbase+blockIdx.z selects 0=Q,1=K,2=V.
__global__ __launch_bounds__(128, 2)
void gemm_proj_kernel(int zbase,
                      const float* __restrict__ q_in, const float* __restrict__ k_in,
                      const float* __restrict__ v_in, const float* __restrict__ bq,
                      const float* __restrict__ bk, const float* __restrict__ bv)
{
    extern __shared__ char smem[];
    const int z  = zbase + blockIdx.z;
    const int bm = blockIdx.y * 128;
    const int bn = blockIdx.x * 128;
    const float* A   = (z == 0) ? q_in : (z == 1) ? k_in : v_in;
    const float* Bia = (z == 0) ? bq : (z == 1) ? bk : bv;
    float* Dst       = (z == 0) ? g_Q : (z == 1) ? g_K : g_V;
    gemm_body<true>(A + (size_t)bm * DD,
                    (const char*)(g_Whi + (size_t)z*DD*DD) + (size_t)bn * 2048,
                    (const char*)(g_Wlo + (size_t)z*DD*DD) + (size_t)bn * 2048,
                    Bia, Dst, bm, bn, smem);
}

__global__ __launch_bounds__(128, 2)
void gemm_out_kernel(const float* __restrict__ bo, float* __restrict__ out)
{
    extern __shared__ char smem[];
    const int bm = blockIdx.y * 128;
    const int bn = blockIdx.x * 128;
    gemm_body<false>(g_X + (size_t)bm * DD,
                     (const char*)(g_Whi + (size_t)3*DD*DD) + (size_t)bn * 2048,
                     (const char*)(g_Wlo + (size_t)3*DD*DD) + (size_t)bn * 2048,
                     bo, out, bm, bn, smem);
}

// ----- Stage A: K^T V partials, double-buffered cp.async -----
__global__ __launch_bounds__(256)
void kv_outer_kernel()
{
    const int bh = blockIdx.x;
    const int sp = blockIdx.y;
    const float* Kh = g_K + (size_t)bh * SS * DK;
    const float* Vh = g_V + (size_t)bh * SS * DK;

    __shared__ float Ks[2][32][68];
    __shared__ float Vs[2][32][68];

    const int tid = threadIdx.x;
    const int tx = tid & 15;
    const int ty = tid >> 4;
    const int lr  = tid >> 4;
    const int lc4 = (tid & 15) * 4;

    const int s0 = sp * (SS / NSPLIT);
    const int NCH = SS / NSPLIT / 32;

    #define KVSTAGE(buf, c) do {                                              \
        _Pragma("unroll")                                                     \
        for (int it = 0; it < 2; ++it) {                                      \
            const int r = lr + it * 16;                                       \
            const size_t go = (size_t)(s0 + (c)*32 + r) * DK + lc4;           \
            cp16(smem_u32(&Ks[buf][r][lc4]), &Kh[go]);                        \
            cp16(smem_u32(&Vs[buf][r][lc4]), &Vh[go]);                        \
        }                                                                     \
    } while (0)

    u64 acc[4][2] = {};

    KVSTAGE(0, 0);
    CP_COMMIT();

    for (int c = 0; c < NCH; ++c) {
        const int buf = c & 1;
        if (c + 1 < NCH) {
            KVSTAGE(buf ^ 1, c + 1);
            CP_COMMIT();
            CP_WAIT(1);
        } else {
            CP_WAIT(0);
        }
        __syncthreads();
        #pragma unroll
        for (int s = 0; s < 32; ++s) {
            float4 a = *(const float4*)&Ks[buf][s][ty*4];
            const u64* vp = (const u64*)&Vs[buf][s][tx*4];
            u64 v0 = vp[0], v1 = vp[1];
            fma2(acc[0][0], bcast2(a.x), v0); fma2(acc[0][1], bcast2(a.x), v1);
            fma2(acc[1][0], bcast2(a.y), v0); fma2(acc[1][1], bcast2(a.y), v1);
            fma2(acc[2][0], bcast2(a.z), v0); fma2(acc[2][1], bcast2(a.z), v1);
            fma2(acc[3][0], bcast2(a.w), v0); fma2(acc[3][1], bcast2(a.w), v1);
        }
        __syncthreads();
    }
    #undef KVSTAGE

    float* dst = g_Tp + (size_t)(sp * 32 + bh) * 4096;
    #pragma unroll
    for (int i = 0; i < 4; ++i) {
        float2 p0 = unpack2(acc[i][0]);
        float2 p1 = unpack2(acc[i][1]);
        float4 o = { p0.x, p0.y, p1.x, p1.y };
        *(float4*)&dst[(ty*4 + i) * 64 + tx*4] = o;
    }
}

__global__ __launch_bounds__(128)
void reduce_T_kernel()
{
    const int bh = blockIdx.x;
    const int i  = blockIdx.y * 128 + threadIdx.x;
    float4 s = {0.f, 0.f, 0.f, 0.f};
    #pragma unroll
    for (int sp = 0; sp < NSPLIT; ++sp) {
        const float4 p = *(const float4*)&g_Tp[(size_t)(sp*32 + bh)*4096 + i*4];
        s.x += p.x; s.y += p.y; s.z += p.z; s.w += p.w;
    }
    float4 o = { s.x*0.125f, s.y*0.125f, s.z*0.125f, s.w*0.125f };
    *(float4*)&g_T[(size_t)bh*4096 + i*4] = o;
}

__global__ __launch_bounds__(256)
void mask_scan_kernel(const int* __restrict__ mask)
{
    const int kt = blockIdx.x, qt = blockIdx.y, b = blockIdx.z;
    const int* mp = mask + (size_t)b * SS * SS + (size_t)qt * 64 * SS + kt * 64;
    __shared__ int s_bad;
    if (threadIdx.x == 0) s_bad = 0;
    __syncthreads();
    const int r  = threadIdx.x >> 2;
    const int c0 = (threadIdx.x & 3) * 16;
    bool bad = false;
    #pragma unroll
    for (int j = 0; j < 4; ++j) {
        int4 v = *(const int4*)&mp[(size_t)r * SS + c0 + j*4];
        if (v.x == 0 || v.y == 0 || v.z == 0 || v.w == 0) bad = true;
    }
    if (bad) s_bad = 1;
    __syncthreads();
    if (threadIdx.x == 0) g_mflag[(b*32 + qt)*32 + kt] = s_bad;
}

// ----- Stage B: qkv = Q @ T (+ corrections), softmax over DK, write fp32 X -----
__global__ __launch_bounds__(256)
void qt_softmax_kernel(const int* __restrict__ mask)
{
    const int qt = blockIdx.x;
    const int bh = blockIdx.y;
    const int b  = bh >> 4;
    const int h  = bh & (HH - 1);
    const int q0 = qt * 64;

    const float* Qh = g_Q + (size_t)bh * SS * DK;

    __shared__ float Qs[64][68];
    __shared__ float Ts[64][68];
    __shared__ float CK[16][68];
    __shared__ float CV[16][68];
    __shared__ int s_flags[32];
    __shared__ int s_any;

    const int tid = threadIdx.x;

    #pragma unroll
    for (int it = 0; it < 4; ++it) {
        const int lin = tid + it * 256;
        const int d4 = lin >> 6;
        const int q  = lin & 63;
        float4 v = *(const float4*)&Qh[(size_t)(q0 + q) * DK + d4*4];
        Qs[d4*4+0][q] = v.x; Qs[d4*4+1][q] = v.y;
        Qs[d4*4+2][q] = v.z; Qs[d4*4+3][q] = v.w;
    }
    {
        const float* Tb = g_T + (size_t)bh * 4096;
        #pragma unroll
        for (int it = 0; it < 4; ++it) {
            const int lin = tid + it * 256;
            const int d1 = lin >> 4;
            const int c4 = (lin & 15) * 4;
            *(float4*)&Ts[d1][c4] = *(const float4*)(Tb + d1 * 64 + c4);
        }
    }

    if (tid == 0) s_any = 0;
    __syncthreads();
    if (tid < 32) {
        int f = g_mflag[(b*32 + qt)*32 + tid];
        s_flags[tid] = f;
        if (f) s_any = 1;
    }
    __syncthreads();

    const int tx = tid & 15;
    const int ty = tid >> 4;

    u64 acc[4][2] = {};
    #pragma unroll
    for (int d1 = 0; d1 < 64; ++d1) {
        float4 a = *(const float4*)&Qs[d1][ty*4];
        const u64* tp = (const u64*)&Ts[d1][tx*4];
        u64 t0 = tp[0], t1 = tp[1];
        fma2(acc[0][0], bcast2(a.x), t0); fma2(acc[0][1], bcast2(a.x), t1);
        fma2(acc[1][0], bcast2(a.y), t0); fma2(acc[1][1], bcast2(a.y), t1);
        fma2(acc[2][0], bcast2(a.z), t0); fma2(acc[2][1], bcast2(a.z), t1);
        fma2(acc[3][0], bcast2(a.w), t0); fma2(acc[3][1], bcast2(a.w), t1);
    }

    if (s_any) {
        const float* Kh = g_K + (size_t)bh * SS * DK;
        const float* Vh = g_V + (size_t)bh * SS * DK;
        const int* mb = mask + (size_t)b * SS * SS;
        for (int kt = 0; kt < 32; ++kt) {
            if (!s_flags[kt]) continue;
            for (int sub = 0; sub < 4; ++sub) {
                const int kbase = kt*64 + sub*16;
                __syncthreads();
                {
                    const int r  = tid >> 4;
                    const int c4 = (tid & 15) * 4;
                    *(float4*)&CK[r][c4] = *(const float4*)&Kh[(size_t)(kbase + r) * DK + c4];
                    *(float4*)&CV[r][c4] = *(const float4*)&Vh[(size_t)(kbase + r) * DK + c4];
                }
                __syncthreads();
                for (int kk = 0; kk < 16; ++kk) {
                    const u64* vp = (const u64*)&CV[kk][tx*4];
                    u64 v0 = vp[0], v1 = vp[1];
                    #pragma unroll
                    for (int qi = 0; qi < 4; ++qi) {
                        const int q = q0 + ty*4 + qi;
                        if (mb[(size_t)q * SS + kbase + kk] == 0) {
                            float s = 0.f;
                            for (int d1 = 0; d1 < 64; ++d1)
                                s += Qs[d1][ty*4 + qi] * CK[kk][d1];
                            const float coef = -1e9f - s * 0.125f;
                            u64 cz = bcast2(coef);
                            fma2(acc[qi][0], cz, v0);
                            fma2(acc[qi][1], cz, v1);
                        }
                    }
                }
            }
        }
    }

    #pragma unroll
    for (int i = 0; i < 4; ++i) {
        float2 pa = unpack2(acc[i][0]);
        float2 pb = unpack2(acc[i][1]);
        float v0 = pa.x, v1 = pa.y, v2 = pb.x, v3 = pb.y;
        float m = fmaxf(fmaxf(v0, v1), fmaxf(v2, v3));
        #pragma unroll
        for (int off = 8; off >= 1; off >>= 1)
            m = fmaxf(m, __shfl_xor_sync(0xffffffffu, m, off, 16));
        float e0 = __expf(v0 - m);
        float e1 = __expf(v1 - m);
        float e2 = __expf(v2 - m);
        float e3 = __expf(v3 - m);
        float sum = e0 + e1 + e2 + e3;
        #pragma unroll
        for (int off = 8; off >= 1; off >>= 1)
            sum += __shfl_xor_sync(0xffffffffu, sum, off, 16);
        const float inv = 1.0f / sum;
        float4 o = { e0*inv, e1*inv, e2*inv, e3*inv };
        const int s = q0 + ty*4 + i;
        *(float4*)&g_X[((size_t)b * SS + s) * DD + h * DK + tx*4] = o;
    }
}

// ----- Launch -----
extern "C" void kernel_launch(void* const* d_in, const int* in_sizes, int n_in,
                              void* d_out, int out_size)
{
    (void)in_sizes; (void)n_in; (void)out_size;
    const float* k_in = (const float*)d_in[0];
    const float* q_in = (const float*)d_in[1];
    const float* v_in = (const float*)d_in[2];
    const int*   mask = (const int*)  d_in[3];
    const float* Wq = (const float*)d_in[4];
    const float* bq = (const float*)d_in[5];
    const float* Wk = (const float*)d_in[6];
    const float* bk = (const float*)d_in[7];
    const float* Wv = (const float*)d_in[8];
    const float* bv = (const float*)d_in[9];
    const float* Wo = (const float*)d_in[10];
    const float* bo = (const float*)d_in[11];
    float* out = (float*)d_out;

    static bool s_init = false;
    static cudaStream_t s2, s3;
    static cudaEvent_t evF, evJ, evKV, evT;
    if (!s_init) {
        cudaStreamCreate(&s2);
        cudaStreamCreate(&s3);
        cudaEventCreateWithFlags(&evF, cudaEventDisableTiming);
        cudaEventCreateWithFlags(&evJ, cudaEventDisableTiming);
        cudaEventCreateWithFlags(&evKV, cudaEventDisableTiming);
        cudaEventCreateWithFlags(&evT, cudaEventDisableTiming);
        cudaFuncSetAttribute((const void*)gemm_proj_kernel,
                             cudaFuncAttributeMaxDynamicSharedMemorySize, SMEM_GEMM);
        cudaFuncSetAttribute((const void*)gemm_out_kernel,
                             cudaFuncAttributeMaxDynamicSharedMemorySize, SMEM_GEMM);
        cudaFuncSetAttribute((const void*)gemm_proj_kernel,
                             cudaFuncAttributePreferredSharedMemoryCarveout, 100);
        cudaFuncSetAttribute((const void*)gemm_out_kernel,
                             cudaFuncAttributePreferredSharedMemoryCarveout, 100);
        s_init = true;
    }

    const int nW4 = DD * DD / 4;

    // Fork: mask_scan + Wo split depend only on inputs -> side stream s2.
    cudaEventRecord(evF, 0);
    cudaStreamWaitEvent(s2, evF, 0);
    mask_scan_kernel<<<dim3(32, 32, 2), 256, 0, s2>>>(mask);
    split_one_weight_kernel<<<dim3(nW4/256, 1), 256, 0, s2>>>(3, Wq, Wk, Wv, Wo);
    cudaEventRecord(evJ, s2);

    // Main stream: only Wq,Wk,Wv splits gate the projections.
    split_one_weight_kernel<<<dim3(nW4/256, 3), 256>>>(0, Wq, Wk, Wv, Wo);

    // K,V projections first; kv_outer only needs these.
    gemm_proj_kernel<<<dim3(DD/128, BSM/128, 2), 128, SMEM_GEMM>>>(
        1, q_in, k_in, v_in, bq, bk, bv);
    cudaEventRecord(evKV, 0);

    // Q projection on main stream, overlapped with kv_outer/reduce_T on s3.
    gemm_proj_kernel<<<dim3(DD/128, BSM/128, 1), 128, SMEM_GEMM>>>(
        0, q_in, k_in, v_in, bq, bk, bv);

    cudaStreamWaitEvent(s3, evKV, 0);
    kv_outer_kernel<<<dim3(32, NSPLIT), 256, 0, s3>>>();
    reduce_T_kernel<<<dim3(32, 8), 128, 0, s3>>>();
    cudaEventRecord(evT, s3);

    // Join: qt_softmax needs Q (stream 0 order), T (evT), mask flags + Wo (evJ).
    cudaStreamWaitEvent(0, evT, 0);
    cudaStreamWaitEvent(0, evJ, 0);
    qt_softmax_kernel<<<dim3(32, 32), 256>>>(mask);

    gemm_out_kernel<<<dim3(DD/128, BSM/128), 128, SMEM_GEMM>>>(bo, out);
}